// round 3
// baseline (speedup 1.0000x reference)
#include <cuda_runtime.h>
#include <math.h>

// Problem constants: x[8, 256, 128, 128] fp32
#define NPLANES 2048          // B*C
#define HW      16384         // 128*128
#define SM_STRIDE 132         // padded row stride (float4-aligned, conflict-friendly)
#define SM_ROWS   130         // 128 + top/bottom halo
#define SM_FLOATS (SM_ROWS * SM_STRIDE)   // 17160 floats = 68640 B

// Scratch (no allocations allowed)
__device__ float g_p[NPLANES];   // per-plane mean
__device__ float g_h[8 * 64];    // hidden activations
__device__ float g_a[NPLANES];   // sigmoid attention scales

// ---------------------------------------------------------------------------
// K1: per-(b,c) plane mean. 2048 blocks x 256 threads, float4 loads.
// ---------------------------------------------------------------------------
__global__ void __launch_bounds__(256) mean_kernel(const float* __restrict__ x) {
    int plane = blockIdx.x;
    const float4* xp = (const float4*)(x + (size_t)plane * HW);
    int tid = threadIdx.x;
    float s = 0.f;
#pragma unroll
    for (int k = 0; k < 16; k++) {
        float4 v = xp[tid + k * 256];
        s += (v.x + v.y) + (v.z + v.w);
    }
#pragma unroll
    for (int o = 16; o; o >>= 1) s += __shfl_xor_sync(0xffffffffu, s, o);
    __shared__ float red[8];
    if ((tid & 31) == 0) red[tid >> 5] = s;
    __syncthreads();
    if (tid == 0) {
        float t = 0.f;
#pragma unroll
        for (int i = 0; i < 8; i++) t += red[i];
        g_p[plane] = t * (1.0f / 16384.0f);
    }
}

// ---------------------------------------------------------------------------
// K2a: h[b,j] = leaky_relu(sum_c p[b,c] * w1[j,c]), w1: [64,256] row-major.
// 8 blocks (one per batch) x 256 threads; 4 threads cooperate per output j.
// ---------------------------------------------------------------------------
__global__ void __launch_bounds__(256) attn1_kernel(const float* __restrict__ w1) {
    int b = blockIdx.x;
    __shared__ float ps[256];
    int tid = threadIdx.x;
    ps[tid] = g_p[b * 256 + tid];
    __syncthreads();
    int j = tid >> 2, part = tid & 3;
    const float* wr = w1 + j * 256 + part * 64;
    const float* pr = ps + part * 64;
    float s = 0.f;
#pragma unroll
    for (int c = 0; c < 64; c++) s = fmaf(pr[c], wr[c], s);
    s += __shfl_xor_sync(0xffffffffu, s, 1);
    s += __shfl_xor_sync(0xffffffffu, s, 2);
    if (part == 0) g_h[b * 64 + j] = (s > 0.f) ? s : 0.01f * s;
}

// ---------------------------------------------------------------------------
// K2b: a[b,c] = sigmoid(sum_j h[b,j] * w2[c,j]), w2: [256,64] row-major.
// 8 blocks x 256 threads, one thread per output channel.
// ---------------------------------------------------------------------------
__global__ void __launch_bounds__(256) attn2_kernel(const float* __restrict__ w2) {
    int b = blockIdx.x;
    __shared__ float hs[64];
    int tid = threadIdx.x;
    if (tid < 64) hs[tid] = g_h[b * 64 + tid];
    __syncthreads();
    const float* wr = w2 + tid * 64;
    float s = 0.f;
#pragma unroll
    for (int j = 0; j < 64; j++) s = fmaf(hs[j], wr[j], s);
    g_a[b * 256 + tid] = 1.0f / (1.0f + expf(-s));
}

// ---------------------------------------------------------------------------
// K3: per-plane fused  scale -> depthwise 3x3 conv (+bias) -> InstanceNorm ->
// leaky_relu. One block per (b,c) plane, padded smem tile, conv outputs kept
// in registers between the stats pass and the normalize/store pass.
// ---------------------------------------------------------------------------
__global__ void __launch_bounds__(256) main_kernel(const float* __restrict__ x,
                                                   const float* __restrict__ rw,
                                                   const float* __restrict__ rb,
                                                   float* __restrict__ out) {
    extern __shared__ float sm[];
    int bc = blockIdx.x;
    int c = bc & 255;
    int tid = threadIdx.x;
    float a = g_a[bc];

    // Zero the whole padded tile (gives SAME zero-padding at the borders)
    float4* smv = (float4*)sm;
    for (int k = tid; k < SM_FLOATS / 4; k += 256)
        smv[k] = make_float4(0.f, 0.f, 0.f, 0.f);
    __syncthreads();

    // Load plane (float4) scaled by attention, into smem at (+1,+1) offset
    const float4* xp = (const float4*)(x + (size_t)bc * HW);
#pragma unroll
    for (int k = 0; k < 16; k++) {
        int fi = tid + k * 256;        // float4 index within plane
        float4 v = xp[fi];
        int row = fi >> 5;             // 32 float4 per row
        int col = (fi & 31) * 4;
        float* d = sm + (row + 1) * SM_STRIDE + col + 1;
        d[0] = v.x * a; d[1] = v.y * a; d[2] = v.z * a; d[3] = v.w * a;
    }

    // Weights for this channel (broadcast loads, L1-resident)
    float w[9];
#pragma unroll
    for (int i = 0; i < 9; i++) w[i] = rw[c * 9 + i];
    float bias = rb[c];
    __syncthreads();

    // Conv: each thread handles 16 groups of 4 consecutive output columns.
    // Window for output cols [c0..c0+3] = smem cols [c0..c0+5]: aligned
    // LDS.128 + LDS.64 per row (conflict-free), 36 FMA per group.
    float4 yv[16];
    float ssum = 0.f, ssq = 0.f;
#pragma unroll
    for (int k = 0; k < 16; k++) {
        int g = tid + k * 256;
        int r = g >> 5;
        int c0 = (g & 31) * 4;
        const float* base = sm + r * SM_STRIDE + c0;
        float e[3][6];
#pragma unroll
        for (int kh = 0; kh < 3; kh++) {
            float4 q = *(const float4*)(base + kh * SM_STRIDE);
            float2 t = *(const float2*)(base + kh * SM_STRIDE + 4);
            e[kh][0] = q.x; e[kh][1] = q.y; e[kh][2] = q.z;
            e[kh][3] = q.w; e[kh][4] = t.x; e[kh][5] = t.y;
        }
        float4 yq;
        float* yp = (float*)&yq;
#pragma unroll
        for (int j = 0; j < 4; j++) {
            float s = bias;
#pragma unroll
            for (int kh = 0; kh < 3; kh++)
#pragma unroll
                for (int kw = 0; kw < 3; kw++)
                    s = fmaf(e[kh][j + kw], w[kh * 3 + kw], s);
            yp[j] = s;
            ssum += s;
            ssq = fmaf(s, s, ssq);
        }
        yv[k] = yq;
    }

    // Block reduction of sum / sumsq
#pragma unroll
    for (int o = 16; o; o >>= 1) {
        ssum += __shfl_xor_sync(0xffffffffu, ssum, o);
        ssq  += __shfl_xor_sync(0xffffffffu, ssq, o);
    }
    __shared__ float r1[8], r2[8];
    __shared__ float s_mu, s_rs;
    if ((tid & 31) == 0) { r1[tid >> 5] = ssum; r2[tid >> 5] = ssq; }
    __syncthreads();
    if (tid == 0) {
        float t1 = 0.f, t2 = 0.f;
#pragma unroll
        for (int i = 0; i < 8; i++) { t1 += r1[i]; t2 += r2[i]; }
        float mu = t1 * (1.0f / 16384.0f);
        float var = t2 * (1.0f / 16384.0f) - mu * mu;
        s_mu = mu;
        s_rs = rsqrtf(var + 1e-5f);
    }
    __syncthreads();
    float mu = s_mu, rs = s_rs;

    // Normalize + leaky relu + coalesced float4 stores
    float4* op = (float4*)(out + (size_t)bc * HW);
#pragma unroll
    for (int k = 0; k < 16; k++) {
        int g = tid + k * 256;
        float4 v = yv[k];
        float* vp = (float*)&v;
#pragma unroll
        for (int j = 0; j < 4; j++) {
            float t = (vp[j] - mu) * rs;
            vp[j] = (t > 0.f) ? t : 0.01f * t;
        }
        op[g] = v;
    }
}

// ---------------------------------------------------------------------------
extern "C" void kernel_launch(void* const* d_in, const int* in_sizes, int n_in,
                              void* d_out, int out_size) {
    const float* x  = (const float*)d_in[0];
    const float* w1 = (const float*)d_in[1];   // [64, 256]
    const float* w2 = (const float*)d_in[2];   // [256, 64]
    const float* rw = (const float*)d_in[3];   // [256, 1, 3, 3]
    const float* rb = (const float*)d_in[4];   // [256]
    float* out = (float*)d_out;

    // 68640 B dynamic smem > 48 KB default limit (idempotent, capture-safe)
    cudaFuncSetAttribute(main_kernel, cudaFuncAttributeMaxDynamicSharedMemorySize,
                         SM_FLOATS * (int)sizeof(float));

    mean_kernel<<<NPLANES, 256>>>(x);
    attn1_kernel<<<8, 256>>>(w1);
    attn2_kernel<<<8, 256>>>(w2);
    main_kernel<<<NPLANES, 256, SM_FLOATS * sizeof(float)>>>(x, rw, rb, out);
}